// round 5
// baseline (speedup 1.0000x reference)
#include <cuda_runtime.h>
#include <cstdio>

// Problem dims (fixed)
#define BB 64
#define PP 196
#define ENC 2048
#define LL 20
#define TT 19
#define VV 32000
#define HH 512
#define EE 512
#define AA 512

#define PRED_SZ ((size_t)BB * TT * VV)
#define ALPHA_SZ ((size_t)BB * TT * PP)

// ---------------- scratch (device globals; no allocation) ----------------
__device__ int   g_sidx[BB];
__device__ int   g_dlen[BB];
__device__ int   g_ystride;                // 1 = int32 tokens, 2 = int64 (as int32 pairs)
__device__ float g_mean[BB * ENC];
__device__ float g_h[BB * HH];
__device__ float g_c[BB * HH];
__device__ float g_att1[BB * PP * AA];     // 25.7 MB
__device__ float g_att2[BB * AA];
__device__ float g_alpha[BB * PP];
__device__ float g_gate[BB * ENC];
__device__ float g_ctx[BB * ENC];
__device__ float g_gates[BB * 4 * HH];

__device__ __forceinline__ float sigmf(float x) { return 1.0f / (1.0f + expf(-x)); }

// Tiled 64xN = 64xK @ (NxK)^T GEMM body. 256 threads, 4x4 per thread micro-tile.
#define GEMM64_BODY(AEXPR, KDIM, WEXPR)                                        \
    __shared__ float As[64][17];                                               \
    __shared__ float Ws[64][17];                                               \
    int tid = threadIdx.x;                                                     \
    int n0 = blockIdx.x * 64;                                                  \
    int tx = tid & 15, ty = tid >> 4;                                          \
    float acc[4][4] = {};                                                      \
    for (int k0 = 0; k0 < (KDIM); k0 += 16) {                                  \
        _Pragma("unroll")                                                      \
        for (int l = 0; l < 4; ++l) {                                          \
            int e = tid + l * 256;                                             \
            int r = e >> 4, kk = e & 15;                                       \
            As[r][kk] = (AEXPR);                                               \
            Ws[r][kk] = (WEXPR);                                               \
        }                                                                      \
        __syncthreads();                                                       \
        _Pragma("unroll")                                                      \
        for (int kk = 0; kk < 16; ++kk) {                                      \
            float a[4], w[4];                                                  \
            _Pragma("unroll")                                                  \
            for (int i = 0; i < 4; ++i) a[i] = As[ty * 4 + i][kk];             \
            _Pragma("unroll")                                                  \
            for (int j = 0; j < 4; ++j) w[j] = Ws[tx * 4 + j][kk];             \
            _Pragma("unroll")                                                  \
            for (int i = 0; i < 4; ++i)                                        \
                _Pragma("unroll")                                              \
                for (int j = 0; j < 4; ++j) acc[i][j] += a[i] * w[j];          \
        }                                                                      \
        __syncthreads();                                                       \
    }

// ---------------- 1) token layout detect + length + stable descending argsort ----------------
__global__ void k_sort(const int* __restrict__ y32, float* __restrict__ out, size_t cap) {
    __shared__ int len[BB];
    __shared__ int stride_s;
    int i = threadIdx.x;
    if (i == 0) {
        // Row 0 has full length L with tokens >= 3. If int64 layout, the high
        // (odd) int32 words are all zero; if int32 layout, slot 1 holds a token.
        int odd = 0;
        for (int l = 0; l < LL; ++l) odd |= (y32[2 * l + 1] != 0);
        stride_s = odd ? 1 : 2;
        g_ystride = stride_s;
    }
    __syncthreads();
    int stride = stride_s;
    if (i < BB) {
        int c = 0;
        for (int l = 0; l < LL; ++l) c += (y32[(i * LL + l) * stride] != 0);
        len[i] = c;
    }
    __syncthreads();
    if (i < BB) {
        int r = 0;
        for (int j = 0; j < BB; ++j)
            r += (len[j] > len[i]) || (len[j] == len[i] && j < i);
        g_sidx[r] = i;
        g_dlen[r] = len[i] - 1;
        size_t base = PRED_SZ + ALPHA_SZ;
        if (base + r < cap)      out[base + r]      = (float)(len[i] - 1);
        if (base + BB + r < cap) out[base + BB + r] = (float)i;
    }
}

// ---------------- 2) mean over P of gathered encoder ----------------
__global__ void k_mean(const float* __restrict__ enc) {
    int b = blockIdx.x;
    int e = blockIdx.y * 256 + threadIdx.x;
    const float* base = enc + (size_t)g_sidx[b] * PP * ENC + e;
    float s = 0.f;
    #pragma unroll 4
    for (int p = 0; p < PP; ++p) s += base[p * ENC];
    g_mean[b * ENC + e] = s * (1.0f / PP);
}

// ---------------- init h0 / c0 : mean @ W^T + b ----------------
__global__ __launch_bounds__(256) void k_init_h(const float* __restrict__ W,
                                                const float* __restrict__ bias) {
    GEMM64_BODY(g_mean[r * ENC + k0 + kk], ENC, W[(n0 + r) * ENC + k0 + kk]);
    #pragma unroll
    for (int i = 0; i < 4; ++i)
        #pragma unroll
        for (int j = 0; j < 4; ++j) {
            int m = ty * 4 + i, n = n0 + tx * 4 + j;
            g_h[m * HH + n] = acc[i][j] + bias[n];
        }
}
__global__ __launch_bounds__(256) void k_init_c(const float* __restrict__ W,
                                                const float* __restrict__ bias) {
    GEMM64_BODY(g_mean[r * ENC + k0 + kk], ENC, W[(n0 + r) * ENC + k0 + kk]);
    #pragma unroll
    for (int i = 0; i < 4; ++i)
        #pragma unroll
        for (int j = 0; j < 4; ++j) {
            int m = ty * 4 + i, n = n0 + tx * 4 + j;
            g_c[m * HH + n] = acc[i][j] + bias[n];
        }
}

// ---------------- att2 = h @ hidden2att_W^T (no bias) ----------------
__global__ __launch_bounds__(256) void k_att2(const float* __restrict__ W) {
    GEMM64_BODY(g_h[r * HH + k0 + kk], HH, W[(n0 + r) * HH + k0 + kk]);
    #pragma unroll
    for (int i = 0; i < 4; ++i)
        #pragma unroll
        for (int j = 0; j < 4; ++j)
            g_att2[(ty * 4 + i) * AA + n0 + tx * 4 + j] = acc[i][j];
}

// ---------------- gate = sigmoid(h @ f_beta_W^T + b) ----------------
__global__ __launch_bounds__(256) void k_fgate(const float* __restrict__ W,
                                               const float* __restrict__ bias) {
    GEMM64_BODY(g_h[r * HH + k0 + kk], HH, W[(n0 + r) * HH + k0 + kk]);
    #pragma unroll
    for (int i = 0; i < 4; ++i)
        #pragma unroll
        for (int j = 0; j < 4; ++j) {
            int m = ty * 4 + i, n = n0 + tx * 4 + j;
            g_gate[m * ENC + n] = sigmf(acc[i][j] + bias[n]);
        }
}

// ---------------- att1 = enc_sorted @ enc2att_W^T (M=12544,N=512,K=2048) ----------------
__global__ __launch_bounds__(256) void k_att1(const float* __restrict__ enc,
                                              const float* __restrict__ Wq) {
    __shared__ int rowOff[64];
    {
        int m0 = blockIdx.y * 64;
        if (threadIdx.x < 64) {
            int m = m0 + threadIdx.x;
            int b = m / PP, p = m % PP;
            rowOff[threadIdx.x] = (g_sidx[b] * PP + p) * ENC;
        }
        __syncthreads();
    }
    GEMM64_BODY(enc[rowOff[r] + k0 + kk], ENC, Wq[(n0 + r) * ENC + k0 + kk]);
    int m0 = blockIdx.y * 64;
    #pragma unroll
    for (int i = 0; i < 4; ++i)
        #pragma unroll
        for (int j = 0; j < 4; ++j)
            g_att1[(m0 + ty * 4 + i) * AA + n0 + tx * 4 + j] = acc[i][j];
}

// ---------------- score + softmax + alpha (per batch row) ----------------
__global__ __launch_bounds__(256) void k_score(const float* __restrict__ attW,
                                               const float* __restrict__ attb,
                                               float* __restrict__ out, size_t cap, int t) {
    __shared__ float a2[AA];
    __shared__ float aw[AA];
    __shared__ float sc[PP];
    __shared__ float red[2];
    int b = blockIdx.x, tid = threadIdx.x;
    for (int i = tid; i < AA; i += 256) { a2[i] = g_att2[b * AA + i]; aw[i] = attW[i]; }
    __syncthreads();
    int w = tid >> 5, lane = tid & 31;
    for (int p = w; p < PP; p += 8) {
        const float* base = g_att1 + (b * PP + p) * AA;
        float s = 0.f;
        for (int a0 = lane; a0 < AA; a0 += 32) {
            float v = base[a0] + a2[a0];
            s += fmaxf(v, 0.f) * aw[a0];
        }
        #pragma unroll
        for (int o = 16; o; o >>= 1) s += __shfl_down_sync(0xFFFFFFFFu, s, o);
        if (lane == 0) sc[p] = s + attb[0];
    }
    __syncthreads();
    if (w == 0) {
        float mx = -1e30f;
        for (int p = lane; p < PP; p += 32) mx = fmaxf(mx, sc[p]);
        #pragma unroll
        for (int o = 16; o; o >>= 1) mx = fmaxf(mx, __shfl_xor_sync(0xFFFFFFFFu, mx, o));
        float sm = 0.f;
        for (int p = lane; p < PP; p += 32) sm += expf(sc[p] - mx);
        #pragma unroll
        for (int o = 16; o; o >>= 1) sm += __shfl_xor_sync(0xFFFFFFFFu, sm, o);
        if (lane == 0) { red[0] = mx; red[1] = 1.0f / sm; }
    }
    __syncthreads();
    float mx = red[0], inv = red[1];
    bool act = g_dlen[b] > t;
    for (int p = tid; p < PP; p += 256) {
        float al = expf(sc[p] - mx) * inv;
        g_alpha[b * PP + p] = al;
        size_t idx = PRED_SZ + (size_t)(b * TT + t) * PP + p;
        if (idx < cap) out[idx] = act ? al : 0.f;
    }
}

// ---------------- context: ctx = gate * (alpha @ enc) ----------------
__global__ void k_ctx(const float* __restrict__ enc) {
    __shared__ float al[PP];
    int b = blockIdx.x;
    int e = blockIdx.y * 256 + threadIdx.x;
    if (threadIdx.x < PP) al[threadIdx.x] = g_alpha[b * PP + threadIdx.x];
    __syncthreads();
    const float* base = enc + (size_t)g_sidx[b] * PP * ENC + e;
    float s = 0.f;
    #pragma unroll 4
    for (int p = 0; p < PP; ++p) s += al[p] * base[p * ENC];
    g_ctx[b * ENC + e] = g_gate[b * ENC + e] * s;
}

// ---------------- LSTM gates GEMM: [emb | ctx | h] @ [W_ih ; W_hh]^T ----------------
__global__ __launch_bounds__(256) void k_gates(const int* __restrict__ y32,
                                               const float* __restrict__ emb,
                                               const float* __restrict__ Wih,
                                               const float* __restrict__ bih,
                                               const float* __restrict__ Whh,
                                               const float* __restrict__ bhh,
                                               int t) {
    __shared__ int tokOff[64];
    if (threadIdx.x < 64) {
        int tok = y32[(g_sidx[threadIdx.x] * LL + t) * g_ystride];
        tok = max(0, min(tok, VV - 1));   // defensive clamp: never gather wild
        tokOff[threadIdx.x] = tok * EE;
    }
    __syncthreads();
    GEMM64_BODY(
        ((k0 + kk) < EE ? emb[tokOff[r] + (k0 + kk)]
         : (k0 + kk) < EE + ENC ? g_ctx[r * ENC + (k0 + kk - EE)]
                                : g_h[r * HH + (k0 + kk - EE - ENC)]),
        (EE + ENC + HH),
        ((k0 + kk) < EE + ENC ? Wih[(n0 + r) * (EE + ENC) + (k0 + kk)]
                              : Whh[(n0 + r) * HH + (k0 + kk - EE - ENC)]));
    #pragma unroll
    for (int i = 0; i < 4; ++i)
        #pragma unroll
        for (int j = 0; j < 4; ++j) {
            int m = ty * 4 + i, n = n0 + tx * 4 + j;
            g_gates[m * (4 * HH) + n] = acc[i][j] + bih[n] + bhh[n];
        }
}

// ---------------- LSTM elementwise (only active rows update) ----------------
__global__ void k_lstm(int t) {
    int b = blockIdx.x, j = threadIdx.x;
    if (g_dlen[b] <= t) return;
    const float* g = g_gates + b * 4 * HH;
    float ig = sigmf(g[j]);
    float fg = sigmf(g[HH + j]);
    float gg = tanhf(g[2 * HH + j]);
    float og = sigmf(g[3 * HH + j]);
    float c = fg * g_c[b * HH + j] + ig * gg;
    g_c[b * HH + j] = c;
    g_h[b * HH + j] = og * tanhf(c);
}

// ---------------- logits GEMM + masked bounded write ----------------
__global__ __launch_bounds__(256) void k_logits(const float* __restrict__ fcW,
                                                const float* __restrict__ fcb,
                                                float* __restrict__ out, size_t cap, int t) {
    GEMM64_BODY(g_h[r * HH + k0 + kk], HH, fcW[(n0 + r) * HH + k0 + kk]);
    #pragma unroll
    for (int i = 0; i < 4; ++i) {
        int m = ty * 4 + i;
        bool act = g_dlen[m] > t;
        #pragma unroll
        for (int j = 0; j < 4; ++j) {
            int n = n0 + tx * 4 + j;
            float v = acc[i][j] + fcb[n];
            size_t idx = ((size_t)m * TT + t) * VV + n;
            if (idx < cap) out[idx] = act ? v : 0.f;
        }
    }
}

// ---------------- launch ----------------
extern "C" void kernel_launch(void* const* d_in, const int* in_sizes, int n_in,
                              void* d_out, int out_size) {
    // Diagnostics: sizes land in the bench log either way (host-side, capture-safe).
    fprintf(stderr, "[kl] n_in=%d out_size=%d sizes:", n_in, out_size);
    for (int i = 0; i < n_in; ++i) fprintf(stderr, " %d", in_sizes[i]);
    fprintf(stderr, "\n");
    if (n_in < 19) return;  // wrong input layout: fail cleanly with diagnostics above

    const float* enc  = (const float*)d_in[0];
    const int*   y32  = (const int*)d_in[1];     // int32 tokens OR int64 viewed as pairs (autodetected)
    const float* emb  = (const float*)d_in[2];
    const float* e2aW = (const float*)d_in[3];
    const float* h2aW = (const float*)d_in[4];
    const float* attW = (const float*)d_in[5];
    const float* attb = (const float*)d_in[6];
    const float* fbW  = (const float*)d_in[7];
    const float* fbb  = (const float*)d_in[8];
    const float* Wih  = (const float*)d_in[9];
    const float* bih  = (const float*)d_in[10];
    const float* Whh  = (const float*)d_in[11];
    const float* bhh  = (const float*)d_in[12];
    const float* fcW  = (const float*)d_in[13];
    const float* fcb  = (const float*)d_in[14];
    const float* ihW  = (const float*)d_in[15];
    const float* ihb  = (const float*)d_in[16];
    const float* icW  = (const float*)d_in[17];
    const float* icb  = (const float*)d_in[18];

    float* out = (float*)d_out;
    size_t cap = (size_t)out_size;

    k_sort<<<1, 64>>>(y32, out, cap);
    k_mean<<<dim3(BB, ENC / 256), 256>>>(enc);
    k_init_h<<<HH / 64, 256>>>(ihW, ihb);
    k_init_c<<<HH / 64, 256>>>(icW, icb);
    k_att1<<<dim3(AA / 64, (BB * PP) / 64), 256>>>(enc, e2aW);

    for (int t = 0; t < TT; ++t) {
        k_att2<<<AA / 64, 256>>>(h2aW);
        k_score<<<BB, 256>>>(attW, attb, out, cap, t);
        k_fgate<<<ENC / 64, 256>>>(fbW, fbb);
        k_ctx<<<dim3(BB, ENC / 256), 256>>>(enc);
        k_gates<<<(4 * HH) / 64, 256>>>(y32, emb, Wih, bih, Whh, bhh, t);
        k_lstm<<<BB, HH>>>(t);
        k_logits<<<VV / 64, 256>>>(fcW, fcb, out, cap, t);
    }
}

// round 8
// speedup vs baseline: 4.2720x; 4.2720x over previous
#include <cuda_runtime.h>

// Problem dims (fixed)
#define BB 64
#define PP 196
#define ENC 2048
#define LL 20
#define TT 19
#define VV 32000
#define HH 512
#define EE 512
#define AA 512

#define PRED_SZ ((size_t)BB * TT * VV)
#define ALPHA_SZ ((size_t)BB * TT * PP)

// GEMM tile config
#define TM 64
#define TN 128
#define TK 16

// K-split factors
#define SP_INIT 8   // K=2048 -> chunks of 256
#define SP_ATT2 4   // K=512  -> chunks of 128
#define SP_FG   2   // K=512  -> chunks of 256
#define SP_GT   8   // K=3072 -> chunks of 384

// ---------------- scratch (device globals; no allocation) ----------------
__device__ int   g_sidx[BB];
__device__ int   g_dlen[BB];
__device__ int   g_ystride;
__device__ float g_mean[BB * ENC];
__device__ float g_h[BB * HH];
__device__ float g_c[BB * HH];
__device__ float g_att1[BB * PP * AA];            // 25.7 MB
__device__ float g_alpha[BB * PP];
__device__ float g_ctx[BB * ENC];
__device__ float g_initP[SP_INIT * BB * 1024];    // h|c partials
__device__ float g_att2P[SP_ATT2 * BB * AA];
__device__ float g_gateP[SP_FG * BB * ENC];
__device__ float g_gatesP[SP_GT * BB * 4 * HH];

__device__ __forceinline__ float sigmf(float x) { return 1.0f / (1.0f + expf(-x)); }

// ---------------- GEMM body: C[64, TN-block] over K chunk ----------------
// AFETCH4(row,k): float4 of A[row][k..k+3], row 0..63, k absolute.
// WFETCH4(row,k): float4 of W[n0+row][k..k+3], row 0..TN-1.
#define GEMM2_BODY(AFETCH4, WFETCH4, KSTART, KTILES)                            \
    __shared__ float As[2][TK][TM + 4];                                         \
    __shared__ float Ws[2][TK][TN + 4];                                         \
    int tid = threadIdx.x;                                                      \
    int tx = tid & 31, ty = tid >> 5;                                           \
    int n0 = blockIdx.x * TN;                                                   \
    int arow = tid >> 2, kq = tid & 3;                                          \
    int brow0 = tid >> 2, brow1 = (tid >> 2) + 64;                              \
    float acc[8][4] = {};                                                       \
    float4 rA, rB0, rB1;                                                        \
    {                                                                           \
        int k = (KSTART) + kq * 4;                                              \
        rA = AFETCH4(arow, k);                                                  \
        rB0 = WFETCH4(brow0, k);                                                \
        rB1 = WFETCH4(brow1, k);                                                \
    }                                                                           \
    As[0][kq * 4 + 0][arow] = rA.x;  As[0][kq * 4 + 1][arow] = rA.y;            \
    As[0][kq * 4 + 2][arow] = rA.z;  As[0][kq * 4 + 3][arow] = rA.w;            \
    Ws[0][kq * 4 + 0][brow0] = rB0.x; Ws[0][kq * 4 + 1][brow0] = rB0.y;         \
    Ws[0][kq * 4 + 2][brow0] = rB0.z; Ws[0][kq * 4 + 3][brow0] = rB0.w;         \
    Ws[0][kq * 4 + 0][brow1] = rB1.x; Ws[0][kq * 4 + 1][brow1] = rB1.y;         \
    Ws[0][kq * 4 + 2][brow1] = rB1.z; Ws[0][kq * 4 + 3][brow1] = rB1.w;         \
    __syncthreads();                                                            \
    for (int tile = 0; tile < (KTILES); ++tile) {                               \
        int buf = tile & 1;                                                     \
        bool more = (tile + 1) < (KTILES);                                      \
        if (more) {                                                             \
            int k = (KSTART) + (tile + 1) * TK + kq * 4;                        \
            rA = AFETCH4(arow, k);                                              \
            rB0 = WFETCH4(brow0, k);                                            \
            rB1 = WFETCH4(brow1, k);                                            \
        }                                                                       \
        _Pragma("unroll")                                                       \
        for (int kk = 0; kk < TK; ++kk) {                                       \
            float4 a0 = *(const float4*)&As[buf][kk][ty * 8];                   \
            float4 a1 = *(const float4*)&As[buf][kk][ty * 8 + 4];               \
            float4 wv = *(const float4*)&Ws[buf][kk][tx * 4];                   \
            float av[8] = {a0.x, a0.y, a0.z, a0.w, a1.x, a1.y, a1.z, a1.w};     \
            float wr[4] = {wv.x, wv.y, wv.z, wv.w};                             \
            _Pragma("unroll")                                                   \
            for (int i = 0; i < 8; ++i)                                         \
                _Pragma("unroll")                                               \
                for (int j = 0; j < 4; ++j) acc[i][j] += av[i] * wr[j];         \
        }                                                                       \
        __syncthreads();                                                        \
        if (more) {                                                             \
            int nb = buf ^ 1;                                                   \
            As[nb][kq * 4 + 0][arow] = rA.x;  As[nb][kq * 4 + 1][arow] = rA.y;  \
            As[nb][kq * 4 + 2][arow] = rA.z;  As[nb][kq * 4 + 3][arow] = rA.w;  \
            Ws[nb][kq * 4 + 0][brow0] = rB0.x; Ws[nb][kq * 4 + 1][brow0] = rB0.y;\
            Ws[nb][kq * 4 + 2][brow0] = rB0.z; Ws[nb][kq * 4 + 3][brow0] = rB0.w;\
            Ws[nb][kq * 4 + 0][brow1] = rB1.x; Ws[nb][kq * 4 + 1][brow1] = rB1.y;\
            Ws[nb][kq * 4 + 2][brow1] = rB1.z; Ws[nb][kq * 4 + 3][brow1] = rB1.w;\
            __syncthreads();                                                    \
        }                                                                       \
    }

#define LD4(p) (*(const float4*)&(p))

// ---------------- sort / layout detect ----------------
__global__ void k_sort(const int* __restrict__ y32, float* __restrict__ out, size_t cap) {
    __shared__ int len[BB];
    __shared__ int stride_s;
    int i = threadIdx.x;
    if (i == 0) {
        int odd = 0;
        for (int l = 0; l < LL; ++l) odd |= (y32[2 * l + 1] != 0);
        stride_s = odd ? 1 : 2;
        g_ystride = stride_s;
    }
    __syncthreads();
    int stride = stride_s;
    if (i < BB) {
        int c = 0;
        for (int l = 0; l < LL; ++l) c += (y32[(i * LL + l) * stride] != 0);
        len[i] = c;
    }
    __syncthreads();
    if (i < BB) {
        int r = 0;
        for (int j = 0; j < BB; ++j)
            r += (len[j] > len[i]) || (len[j] == len[i] && j < i);
        g_sidx[r] = i;
        g_dlen[r] = len[i] - 1;
        size_t base = PRED_SZ + ALPHA_SZ;
        if (base + r < cap)      out[base + r]      = (float)(len[i] - 1);
        if (base + BB + r < cap) out[base + BB + r] = (float)i;
    }
}

// ---------------- mean over P ----------------
__global__ void k_mean(const float* __restrict__ enc) {
    int b = blockIdx.x;
    int e = blockIdx.y * 256 + threadIdx.x;
    const float* base = enc + (size_t)g_sidx[b] * PP * ENC + e;
    float s = 0.f;
    #pragma unroll 8
    for (int p = 0; p < PP; ++p) s += base[p * ENC];
    g_mean[b * ENC + e] = s * (1.0f / PP);
}

// ---------------- init h0/c0 fused GEMM (N=1024), K-split x8 ----------------
__global__ __launch_bounds__(256) void k_init_gemm(const float* __restrict__ ihW,
                                                   const float* __restrict__ icW) {
    int z = blockIdx.z;
#define A_INIT(row, k) LD4(g_mean[(row) * ENC + (k)])
#define W_INIT(row, k) ((n0 + (row)) < HH ? LD4(ihW[(n0 + (row)) * ENC + (k)]) \
                                          : LD4(icW[(n0 + (row) - HH) * ENC + (k)]))
    GEMM2_BODY(A_INIT, W_INIT, z * (ENC / SP_INIT), (ENC / SP_INIT) / TK);
    float* P = g_initP + (size_t)z * BB * 1024;
    #pragma unroll
    for (int i = 0; i < 8; ++i) {
        int m = ty * 8 + i;
        *(float4*)&P[m * 1024 + n0 + tx * 4] =
            make_float4(acc[i][0], acc[i][1], acc[i][2], acc[i][3]);
    }
#undef A_INIT
#undef W_INIT
}

__global__ void k_init_red(const float* __restrict__ ihb, const float* __restrict__ icb) {
    int b = blockIdx.x, n = threadIdx.x;    // 1024 threads
    float s = 0.f;
    #pragma unroll
    for (int z = 0; z < SP_INIT; ++z) s += g_initP[((size_t)z * BB + b) * 1024 + n];
    if (n < HH) g_h[b * HH + n] = s + ihb[n];
    else        g_c[b * HH + (n - HH)] = s + icb[n - HH];
}

// ---------------- att1 = enc_sorted @ enc2att_W^T ----------------
__global__ __launch_bounds__(256) void k_att1(const float* __restrict__ enc,
                                              const float* __restrict__ Wq) {
    __shared__ int rowOff[64];
    int m0 = blockIdx.y * 64;
    if (threadIdx.x < 64) {
        int m = m0 + threadIdx.x;
        int b = m / PP, p = m % PP;
        rowOff[threadIdx.x] = (g_sidx[b] * PP + p) * ENC;
    }
    __syncthreads();
#define A_A1(row, k) LD4(enc[rowOff[(row)] + (k)])
#define W_A1(row, k) LD4(Wq[(n0 + (row)) * ENC + (k)])
    GEMM2_BODY(A_A1, W_A1, 0, ENC / TK);
    #pragma unroll
    for (int i = 0; i < 8; ++i) {
        int m = ty * 8 + i;
        *(float4*)&g_att1[(size_t)(m0 + m) * AA + n0 + tx * 4] =
            make_float4(acc[i][0], acc[i][1], acc[i][2], acc[i][3]);
    }
#undef A_A1
#undef W_A1
}

// ---------------- att2 partials: h @ h2aW^T, K-split x4 ----------------
__global__ __launch_bounds__(256) void k_att2(const float* __restrict__ W) {
    int z = blockIdx.z;
#define A_A2(row, k) LD4(g_h[(row) * HH + (k)])
#define W_A2(row, k) LD4(W[(n0 + (row)) * HH + (k)])
    GEMM2_BODY(A_A2, W_A2, z * (HH / SP_ATT2), (HH / SP_ATT2) / TK);
    float* P = g_att2P + (size_t)z * BB * AA;
    #pragma unroll
    for (int i = 0; i < 8; ++i) {
        int m = ty * 8 + i;
        *(float4*)&P[m * AA + n0 + tx * 4] =
            make_float4(acc[i][0], acc[i][1], acc[i][2], acc[i][3]);
    }
#undef A_A2
#undef W_A2
}

// ---------------- score + softmax + alpha ----------------
__global__ __launch_bounds__(512) void k_score(const float* __restrict__ attW,
                                               const float* __restrict__ attb,
                                               float* __restrict__ out, size_t cap, int t) {
    __shared__ float a2[AA];
    __shared__ float aw[AA];
    __shared__ float sc[PP];
    __shared__ float red[2];
    int b = blockIdx.x, tid = threadIdx.x;
    for (int i = tid; i < AA; i += 512) {
        float s = 0.f;
        #pragma unroll
        for (int z = 0; z < SP_ATT2; ++z) s += g_att2P[((size_t)z * BB + b) * AA + i];
        a2[i] = s;
        aw[i] = attW[i];
    }
    __syncthreads();
    int w = tid >> 5, lane = tid & 31;
    for (int p = w; p < PP; p += 16) {
        const float* base = g_att1 + (size_t)(b * PP + p) * AA;
        float s = 0.f;
        #pragma unroll 4
        for (int a0 = lane; a0 < AA; a0 += 32) {
            float v = base[a0] + a2[a0];
            s += fmaxf(v, 0.f) * aw[a0];
        }
        #pragma unroll
        for (int o = 16; o; o >>= 1) s += __shfl_down_sync(0xFFFFFFFFu, s, o);
        if (lane == 0) sc[p] = s + attb[0];
    }
    __syncthreads();
    if (w == 0) {
        float mx = -1e30f;
        for (int p = lane; p < PP; p += 32) mx = fmaxf(mx, sc[p]);
        #pragma unroll
        for (int o = 16; o; o >>= 1) mx = fmaxf(mx, __shfl_xor_sync(0xFFFFFFFFu, mx, o));
        float sm = 0.f;
        for (int p = lane; p < PP; p += 32) sm += expf(sc[p] - mx);
        #pragma unroll
        for (int o = 16; o; o >>= 1) sm += __shfl_xor_sync(0xFFFFFFFFu, sm, o);
        if (lane == 0) { red[0] = mx; red[1] = 1.0f / sm; }
    }
    __syncthreads();
    float mx = red[0], inv = red[1];
    bool act = g_dlen[b] > t;
    for (int p = tid; p < PP; p += 512) {
        float al = expf(sc[p] - mx) * inv;
        g_alpha[b * PP + p] = al;
        size_t idx = PRED_SZ + (size_t)(b * TT + t) * PP + p;
        if (idx < cap) out[idx] = act ? al : 0.f;
    }
}

// ---------------- fgate partials: h @ fbW^T, K-split x2 ----------------
__global__ __launch_bounds__(256) void k_fgate(const float* __restrict__ W) {
    int z = blockIdx.z;
#define A_FG(row, k) LD4(g_h[(row) * HH + (k)])
#define W_FG(row, k) LD4(W[(n0 + (row)) * HH + (k)])
    GEMM2_BODY(A_FG, W_FG, z * (HH / SP_FG), (HH / SP_FG) / TK);
    float* P = g_gateP + (size_t)z * BB * ENC;
    #pragma unroll
    for (int i = 0; i < 8; ++i) {
        int m = ty * 8 + i;
        *(float4*)&P[m * ENC + n0 + tx * 4] =
            make_float4(acc[i][0], acc[i][1], acc[i][2], acc[i][3]);
    }
#undef A_FG
#undef W_FG
}

// ---------------- context: ctx = sigmoid(gateSum+b) * (alpha @ enc) ----------------
__global__ void k_ctx(const float* __restrict__ enc, const float* __restrict__ fbb) {
    __shared__ float al[PP];
    int b = blockIdx.x;
    int e = blockIdx.y * 256 + threadIdx.x;
    if (threadIdx.x < PP) al[threadIdx.x] = g_alpha[b * PP + threadIdx.x];
    __syncthreads();
    const float* base = enc + (size_t)g_sidx[b] * PP * ENC + e;
    float s = 0.f;
    #pragma unroll 8
    for (int p = 0; p < PP; ++p) s += al[p] * base[p * ENC];
    float gr = g_gateP[b * ENC + e] + g_gateP[(size_t)BB * ENC + b * ENC + e] + fbb[e];
    g_ctx[b * ENC + e] = sigmf(gr) * s;
}

// ---------------- LSTM gates GEMM partials, K-split x8 ----------------
__global__ __launch_bounds__(256) void k_gates(const int* __restrict__ y32,
                                               const float* __restrict__ emb,
                                               const float* __restrict__ Wih,
                                               const float* __restrict__ Whh,
                                               int t) {
    __shared__ int tokOff[64];
    if (threadIdx.x < 64) {
        int tok = y32[(g_sidx[threadIdx.x] * LL + t) * g_ystride];
        tok = max(0, min(tok, VV - 1));
        tokOff[threadIdx.x] = tok * EE;
    }
    __syncthreads();
    int z = blockIdx.z;
#define A_GT(row, k) ((k) < EE ? LD4(emb[tokOff[(row)] + (k)])                       \
                     : (k) < EE + ENC ? LD4(g_ctx[(row) * ENC + ((k) - EE)])         \
                                      : LD4(g_h[(row) * HH + ((k) - EE - ENC)]))
#define W_GT(row, k) ((k) < EE + ENC ? LD4(Wih[(size_t)(n0 + (row)) * (EE + ENC) + (k)]) \
                                     : LD4(Whh[(n0 + (row)) * HH + ((k) - EE - ENC)]))
    GEMM2_BODY(A_GT, W_GT, z * ((EE + ENC + HH) / SP_GT), ((EE + ENC + HH) / SP_GT) / TK);
    float* P = g_gatesP + (size_t)z * BB * 4 * HH;
    #pragma unroll
    for (int i = 0; i < 8; ++i) {
        int m = ty * 8 + i;
        *(float4*)&P[m * (4 * HH) + n0 + tx * 4] =
            make_float4(acc[i][0], acc[i][1], acc[i][2], acc[i][3]);
    }
#undef A_GT
#undef W_GT
}

// ---------------- LSTM: sum gate partials + biases, update h/c ----------------
__global__ void k_lstm(const float* __restrict__ bih, const float* __restrict__ bhh, int t) {
    int b = blockIdx.x, j = threadIdx.x;   // 512 threads
    if (g_dlen[b] <= t) return;
    float gs[4];
    #pragma unroll
    for (int gI = 0; gI < 4; ++gI) {
        int n = gI * HH + j;
        float s = bih[n] + bhh[n];
        #pragma unroll
        for (int z = 0; z < SP_GT; ++z)
            s += g_gatesP[((size_t)z * BB + b) * (4 * HH) + n];
        gs[gI] = s;
    }
    float ig = sigmf(gs[0]);
    float fg = sigmf(gs[1]);
    float gg = tanhf(gs[2]);
    float og = sigmf(gs[3]);
    float c = fg * g_c[b * HH + j] + ig * gg;
    g_c[b * HH + j] = c;
    g_h[b * HH + j] = og * tanhf(c);
}

// ---------------- logits GEMM + masked bounded write ----------------
__global__ __launch_bounds__(256) void k_logits(const float* __restrict__ fcW,
                                                const float* __restrict__ fcb,
                                                float* __restrict__ out, size_t cap, int t) {
#define A_LG(row, k) LD4(g_h[(row) * HH + (k)])
#define W_LG(row, k) LD4(fcW[(size_t)(n0 + (row)) * HH + (k)])
    GEMM2_BODY(A_LG, W_LG, 0, HH / TK);
    #pragma unroll
    for (int i = 0; i < 8; ++i) {
        int m = ty * 8 + i;
        bool act = g_dlen[m] > t;
        #pragma unroll
        for (int j = 0; j < 4; ++j) {
            int n = n0 + tx * 4 + j;
            float v = acc[i][j] + fcb[n];
            size_t idx = ((size_t)m * TT + t) * VV + n;
            if (idx < cap) out[idx] = act ? v : 0.f;
        }
    }
#undef A_LG
#undef W_LG
}

// ---------------- launch ----------------
extern "C" void kernel_launch(void* const* d_in, const int* in_sizes, int n_in,
                              void* d_out, int out_size) {
    if (n_in < 19) return;
    const float* enc  = (const float*)d_in[0];
    const int*   y32  = (const int*)d_in[1];
    const float* emb  = (const float*)d_in[2];
    const float* e2aW = (const float*)d_in[3];
    const float* h2aW = (const float*)d_in[4];
    const float* attW = (const float*)d_in[5];
    const float* attb = (const float*)d_in[6];
    const float* fbW  = (const float*)d_in[7];
    const float* fbb  = (const float*)d_in[8];
    const float* Wih  = (const float*)d_in[9];
    const float* bih  = (const float*)d_in[10];
    const float* Whh  = (const float*)d_in[11];
    const float* bhh  = (const float*)d_in[12];
    const float* fcW  = (const float*)d_in[13];
    const float* fcb  = (const float*)d_in[14];
    const float* ihW  = (const float*)d_in[15];
    const float* ihb  = (const float*)d_in[16];
    const float* icW  = (const float*)d_in[17];
    const float* icb  = (const float*)d_in[18];

    float* out = (float*)d_out;
    size_t cap = (size_t)out_size;

    k_sort<<<1, 64>>>(y32, out, cap);
    k_mean<<<dim3(BB, ENC / 256), 256>>>(enc);
    k_init_gemm<<<dim3(1024 / TN, 1, SP_INIT), 256>>>(ihW, icW);
    k_init_red<<<BB, 1024>>>(ihb, icb);
    k_att1<<<dim3(AA / TN, (BB * PP) / TM), 256>>>(enc, e2aW);

    for (int t = 0; t < TT; ++t) {
        k_att2<<<dim3(AA / TN, 1, SP_ATT2), 256>>>(h2aW);
        k_score<<<BB, 512>>>(attW, attb, out, cap, t);
        k_fgate<<<dim3(ENC / TN, 1, SP_FG), 256>>>(fbW);
        k_ctx<<<dim3(BB, ENC / 256), 256>>>(enc, fbb);
        k_gates<<<dim3((4 * HH) / TN, 1, SP_GT), 256>>>(y32, emb, Wih, Whh, t);
        k_lstm<<<BB, HH>>>(bih, bhh, t);
        k_logits<<<VV / TN, 256>>>(fcW, fcb, out, cap, t);
    }
}

// round 9
// speedup vs baseline: 4.5668x; 1.0690x over previous
#include <cuda_runtime.h>

// Problem dims (fixed)
#define BB 64
#define PP 196
#define ENC 2048
#define LL 20
#define TT 19
#define VV 32000
#define HH 512
#define EE 512
#define AA 512

#define PRED_SZ ((size_t)BB * TT * VV)
#define ALPHA_SZ ((size_t)BB * TT * PP)

// GEMM tile config
#define TM 64
#define TN 128
#define TK 16

// K-split factors
#define SP_INIT 8   // K=2048 -> chunks of 256
#define SP_ATT2 4   // K=512  -> chunks of 128
#define SP_FG   2   // K=512  -> chunks of 256
#define SP_GT   8   // K=3072 -> chunks of 384

// ---------------- scratch (device globals; no allocation) ----------------
__device__ int   g_sidx[BB];
__device__ int   g_dlen[BB];
__device__ int   g_ystride;
__device__ float g_mean[BB * ENC];
__device__ float g_h[BB * HH];
__device__ float g_c[BB * HH];
__device__ float g_att1[BB * PP * AA];            // 25.7 MB
__device__ float g_alpha[BB * PP];
__device__ float g_ctx[BB * ENC];
__device__ float g_initP[SP_INIT * BB * 1024];    // h|c partials
__device__ float g_att2P[SP_ATT2 * BB * AA];
__device__ float g_gateP[SP_FG * BB * ENC];
__device__ float g_gatesP[SP_GT * BB * 4 * HH];

__device__ __forceinline__ float sigmf(float x) { return 1.0f / (1.0f + expf(-x)); }

// ---------------- GEMM body: C[64, TN-block] over K chunk ----------------
// AFETCH4(row,k): float4 of A[row][k..k+3], row 0..63, k absolute.
// WFETCH4(row,k): float4 of W[n0+row][k..k+3], row 0..TN-1.
// TMASK: rows sorted by dec_len desc -> thread's 8 rows all inactive iff
//        g_dlen[ty*8] <= TMASK. Pass -1 to disable masking. Warp-uniform.
#define GEMM2_BODY(AFETCH4, WFETCH4, KSTART, KTILES, TMASK)                     \
    __shared__ float As[2][TK][TM + 4];                                         \
    __shared__ float Ws[2][TK][TN + 4];                                         \
    int tid = threadIdx.x;                                                      \
    int tx = tid & 31, ty = tid >> 5;                                           \
    int n0 = blockIdx.x * TN;                                                   \
    int arow = tid >> 2, kq = tid & 3;                                          \
    int brow0 = tid >> 2, brow1 = (tid >> 2) + 64;                              \
    int myact = (g_dlen[ty * 8] > (TMASK));                                     \
    float acc[8][4] = {};                                                       \
    float4 rA, rB0, rB1;                                                        \
    {                                                                           \
        int k = (KSTART) + kq * 4;                                              \
        rA = AFETCH4(arow, k);                                                  \
        rB0 = WFETCH4(brow0, k);                                                \
        rB1 = WFETCH4(brow1, k);                                                \
    }                                                                           \
    As[0][kq * 4 + 0][arow] = rA.x;  As[0][kq * 4 + 1][arow] = rA.y;            \
    As[0][kq * 4 + 2][arow] = rA.z;  As[0][kq * 4 + 3][arow] = rA.w;            \
    Ws[0][kq * 4 + 0][brow0] = rB0.x; Ws[0][kq * 4 + 1][brow0] = rB0.y;         \
    Ws[0][kq * 4 + 2][brow0] = rB0.z; Ws[0][kq * 4 + 3][brow0] = rB0.w;         \
    Ws[0][kq * 4 + 0][brow1] = rB1.x; Ws[0][kq * 4 + 1][brow1] = rB1.y;         \
    Ws[0][kq * 4 + 2][brow1] = rB1.z; Ws[0][kq * 4 + 3][brow1] = rB1.w;         \
    __syncthreads();                                                            \
    for (int tile = 0; tile < (KTILES); ++tile) {                               \
        int buf = tile & 1;                                                     \
        bool more = (tile + 1) < (KTILES);                                      \
        if (more) {                                                             \
            int k = (KSTART) + (tile + 1) * TK + kq * 4;                        \
            rA = AFETCH4(arow, k);                                              \
            rB0 = WFETCH4(brow0, k);                                            \
            rB1 = WFETCH4(brow1, k);                                            \
        }                                                                       \
        if (myact) {                                                            \
            _Pragma("unroll")                                                   \
            for (int kk = 0; kk < TK; ++kk) {                                   \
                float4 a0 = *(const float4*)&As[buf][kk][ty * 8];               \
                float4 a1 = *(const float4*)&As[buf][kk][ty * 8 + 4];           \
                float4 wv = *(const float4*)&Ws[buf][kk][tx * 4];               \
                float av[8] = {a0.x, a0.y, a0.z, a0.w, a1.x, a1.y, a1.z, a1.w}; \
                float wr[4] = {wv.x, wv.y, wv.z, wv.w};                         \
                _Pragma("unroll")                                               \
                for (int i = 0; i < 8; ++i)                                     \
                    _Pragma("unroll")                                           \
                    for (int j = 0; j < 4; ++j) acc[i][j] += av[i] * wr[j];     \
            }                                                                   \
        }                                                                       \
        __syncthreads();                                                        \
        if (more) {                                                             \
            int nb = buf ^ 1;                                                   \
            As[nb][kq * 4 + 0][arow] = rA.x;  As[nb][kq * 4 + 1][arow] = rA.y;  \
            As[nb][kq * 4 + 2][arow] = rA.z;  As[nb][kq * 4 + 3][arow] = rA.w;  \
            Ws[nb][kq * 4 + 0][brow0] = rB0.x; Ws[nb][kq * 4 + 1][brow0] = rB0.y;\
            Ws[nb][kq * 4 + 2][brow0] = rB0.z; Ws[nb][kq * 4 + 3][brow0] = rB0.w;\
            Ws[nb][kq * 4 + 0][brow1] = rB1.x; Ws[nb][kq * 4 + 1][brow1] = rB1.y;\
            Ws[nb][kq * 4 + 2][brow1] = rB1.z; Ws[nb][kq * 4 + 3][brow1] = rB1.w;\
            __syncthreads();                                                    \
        }                                                                       \
    }

#define LD4(p) (*(const float4*)&(p))

// ---------------- sort / layout detect ----------------
__global__ void k_sort(const int* __restrict__ y32, float* __restrict__ out, size_t cap) {
    __shared__ int len[BB];
    __shared__ int stride_s;
    int i = threadIdx.x;
    if (i == 0) {
        int odd = 0;
        for (int l = 0; l < LL; ++l) odd |= (y32[2 * l + 1] != 0);
        stride_s = odd ? 1 : 2;
        g_ystride = stride_s;
    }
    __syncthreads();
    int stride = stride_s;
    if (i < BB) {
        int c = 0;
        for (int l = 0; l < LL; ++l) c += (y32[(i * LL + l) * stride] != 0);
        len[i] = c;
    }
    __syncthreads();
    if (i < BB) {
        int r = 0;
        for (int j = 0; j < BB; ++j)
            r += (len[j] > len[i]) || (len[j] == len[i] && j < i);
        g_sidx[r] = i;
        g_dlen[r] = len[i] - 1;
        size_t base = PRED_SZ + ALPHA_SZ;
        if (base + r < cap)      out[base + r]      = (float)(len[i] - 1);
        if (base + BB + r < cap) out[base + BB + r] = (float)i;
    }
}

// ---------------- mean over P ----------------
__global__ void k_mean(const float* __restrict__ enc) {
    int b = blockIdx.x;
    int e = blockIdx.y * 256 + threadIdx.x;
    const float* base = enc + (size_t)g_sidx[b] * PP * ENC + e;
    float s = 0.f;
    #pragma unroll 8
    for (int p = 0; p < PP; ++p) s += base[p * ENC];
    g_mean[b * ENC + e] = s * (1.0f / PP);
}

// ---------------- init h0/c0 fused GEMM (N=1024), K-split x8 ----------------
__global__ __launch_bounds__(256) void k_init_gemm(const float* __restrict__ ihW,
                                                   const float* __restrict__ icW) {
    int z = blockIdx.z;
#define A_INIT(row, k) LD4(g_mean[(row) * ENC + (k)])
#define W_INIT(row, k) ((n0 + (row)) < HH ? LD4(ihW[(n0 + (row)) * ENC + (k)]) \
                                          : LD4(icW[(n0 + (row) - HH) * ENC + (k)]))
    GEMM2_BODY(A_INIT, W_INIT, z * (ENC / SP_INIT), (ENC / SP_INIT) / TK, -1);
    float* P = g_initP + (size_t)z * BB * 1024;
    #pragma unroll
    for (int i = 0; i < 8; ++i) {
        int m = ty * 8 + i;
        *(float4*)&P[m * 1024 + n0 + tx * 4] =
            make_float4(acc[i][0], acc[i][1], acc[i][2], acc[i][3]);
    }
#undef A_INIT
#undef W_INIT
}

__global__ void k_init_red(const float* __restrict__ ihb, const float* __restrict__ icb) {
    int b = blockIdx.x, n = threadIdx.x;    // 1024 threads
    float s = 0.f;
    #pragma unroll
    for (int z = 0; z < SP_INIT; ++z) s += g_initP[((size_t)z * BB + b) * 1024 + n];
    if (n < HH) g_h[b * HH + n] = s + ihb[n];
    else        g_c[b * HH + (n - HH)] = s + icb[n - HH];
}

// ---------------- att1 = enc_sorted @ enc2att_W^T ----------------
__global__ __launch_bounds__(256) void k_att1(const float* __restrict__ enc,
                                              const float* __restrict__ Wq) {
    __shared__ int rowOff[64];
    int m0 = blockIdx.y * 64;
    if (threadIdx.x < 64) {
        int m = m0 + threadIdx.x;
        int b = m / PP, p = m % PP;
        rowOff[threadIdx.x] = (g_sidx[b] * PP + p) * ENC;
    }
    __syncthreads();
#define A_A1(row, k) LD4(enc[rowOff[(row)] + (k)])
#define W_A1(row, k) LD4(Wq[(n0 + (row)) * ENC + (k)])
    GEMM2_BODY(A_A1, W_A1, 0, ENC / TK, -1);
    #pragma unroll
    for (int i = 0; i < 8; ++i) {
        int m = ty * 8 + i;
        *(float4*)&g_att1[(size_t)(m0 + m) * AA + n0 + tx * 4] =
            make_float4(acc[i][0], acc[i][1], acc[i][2], acc[i][3]);
    }
#undef A_A1
#undef W_A1
}

// ---------------- att2 partials: h @ h2aW^T, K-split x4, masked by t ----------------
__global__ __launch_bounds__(256) void k_att2(const float* __restrict__ W, int t) {
    int z = blockIdx.z;
#define A_A2(row, k) LD4(g_h[(row) * HH + (k)])
#define W_A2(row, k) LD4(W[(n0 + (row)) * HH + (k)])
    GEMM2_BODY(A_A2, W_A2, z * (HH / SP_ATT2), (HH / SP_ATT2) / TK, t);
    float* P = g_att2P + (size_t)z * BB * AA;
    #pragma unroll
    for (int i = 0; i < 8; ++i) {
        int m = ty * 8 + i;
        *(float4*)&P[m * AA + n0 + tx * 4] =
            make_float4(acc[i][0], acc[i][1], acc[i][2], acc[i][3]);
    }
#undef A_A2
#undef W_A2
}

// ---------------- score + softmax + alpha (skips inactive rows) ----------------
__global__ __launch_bounds__(512) void k_score(const float* __restrict__ attW,
                                               const float* __restrict__ attb,
                                               float* __restrict__ out, size_t cap, int t) {
    __shared__ float a2[AA];
    __shared__ float aw[AA];
    __shared__ float sc[PP];
    __shared__ float red[2];
    int b = blockIdx.x, tid = threadIdx.x;
    if (g_dlen[b] <= t) {           // inactive: just write the required zeros
        for (int p = tid; p < PP; p += 512) {
            size_t idx = PRED_SZ + (size_t)(b * TT + t) * PP + p;
            if (idx < cap) out[idx] = 0.f;
        }
        return;
    }
    for (int i = tid; i < AA; i += 512) {
        float s = 0.f;
        #pragma unroll
        for (int z = 0; z < SP_ATT2; ++z) s += g_att2P[((size_t)z * BB + b) * AA + i];
        a2[i] = s;
        aw[i] = attW[i];
    }
    __syncthreads();
    int w = tid >> 5, lane = tid & 31;
    for (int p = w; p < PP; p += 16) {
        const float* base = g_att1 + (size_t)(b * PP + p) * AA;
        float s = 0.f;
        #pragma unroll 4
        for (int a0 = lane; a0 < AA; a0 += 32) {
            float v = base[a0] + a2[a0];
            s += fmaxf(v, 0.f) * aw[a0];
        }
        #pragma unroll
        for (int o = 16; o; o >>= 1) s += __shfl_down_sync(0xFFFFFFFFu, s, o);
        if (lane == 0) sc[p] = s + attb[0];
    }
    __syncthreads();
    if (w == 0) {
        float mx = -1e30f;
        for (int p = lane; p < PP; p += 32) mx = fmaxf(mx, sc[p]);
        #pragma unroll
        for (int o = 16; o; o >>= 1) mx = fmaxf(mx, __shfl_xor_sync(0xFFFFFFFFu, mx, o));
        float sm = 0.f;
        for (int p = lane; p < PP; p += 32) sm += expf(sc[p] - mx);
        #pragma unroll
        for (int o = 16; o; o >>= 1) sm += __shfl_xor_sync(0xFFFFFFFFu, sm, o);
        if (lane == 0) { red[0] = mx; red[1] = 1.0f / sm; }
    }
    __syncthreads();
    float mx = red[0], inv = red[1];
    for (int p = tid; p < PP; p += 512) {
        float al = expf(sc[p] - mx) * inv;
        g_alpha[b * PP + p] = al;
        size_t idx = PRED_SZ + (size_t)(b * TT + t) * PP + p;
        if (idx < cap) out[idx] = al;
    }
}

// ---------------- fgate partials: h @ fbW^T, K-split x2, masked by t ----------------
__global__ __launch_bounds__(256) void k_fgate(const float* __restrict__ W, int t) {
    int z = blockIdx.z;
#define A_FG(row, k) LD4(g_h[(row) * HH + (k)])
#define W_FG(row, k) LD4(W[(n0 + (row)) * HH + (k)])
    GEMM2_BODY(A_FG, W_FG, z * (HH / SP_FG), (HH / SP_FG) / TK, t);
    float* P = g_gateP + (size_t)z * BB * ENC;
    #pragma unroll
    for (int i = 0; i < 8; ++i) {
        int m = ty * 8 + i;
        *(float4*)&P[m * ENC + n0 + tx * 4] =
            make_float4(acc[i][0], acc[i][1], acc[i][2], acc[i][3]);
    }
#undef A_FG
#undef W_FG
}

// ---------------- context: ctx = sigmoid(gateSum+b) * (alpha @ enc), active b only ----------------
__global__ void k_ctx(const float* __restrict__ enc, const float* __restrict__ fbb, int t) {
    __shared__ float al[PP];
    int b = blockIdx.x;
    if (g_dlen[b] <= t) return;   // inactive: stale ctx only feeds skipped rows
    int e = blockIdx.y * 256 + threadIdx.x;
    if (threadIdx.x < PP) al[threadIdx.x] = g_alpha[b * PP + threadIdx.x];
    __syncthreads();
    const float* base = enc + (size_t)g_sidx[b] * PP * ENC + e;
    float s = 0.f;
    #pragma unroll 8
    for (int p = 0; p < PP; ++p) s += al[p] * base[p * ENC];
    float gr = g_gateP[b * ENC + e] + g_gateP[(size_t)BB * ENC + b * ENC + e] + fbb[e];
    g_ctx[b * ENC + e] = sigmf(gr) * s;
}

// ---------------- LSTM gates GEMM partials, K-split x8, masked by t ----------------
__global__ __launch_bounds__(256) void k_gates(const int* __restrict__ y32,
                                               const float* __restrict__ emb,
                                               const float* __restrict__ Wih,
                                               const float* __restrict__ Whh,
                                               int t) {
    __shared__ int tokOff[64];
    if (threadIdx.x < 64) {
        int tok = y32[(g_sidx[threadIdx.x] * LL + t) * g_ystride];
        tok = max(0, min(tok, VV - 1));
        tokOff[threadIdx.x] = tok * EE;
    }
    __syncthreads();
    int z = blockIdx.z;
#define A_GT(row, k) ((k) < EE ? LD4(emb[tokOff[(row)] + (k)])                       \
                     : (k) < EE + ENC ? LD4(g_ctx[(row) * ENC + ((k) - EE)])         \
                                      : LD4(g_h[(row) * HH + ((k) - EE - ENC)]))
#define W_GT(row, k) ((k) < EE + ENC ? LD4(Wih[(size_t)(n0 + (row)) * (EE + ENC) + (k)]) \
                                     : LD4(Whh[(n0 + (row)) * HH + ((k) - EE - ENC)]))
    GEMM2_BODY(A_GT, W_GT, z * ((EE + ENC + HH) / SP_GT), ((EE + ENC + HH) / SP_GT) / TK, t);
    float* P = g_gatesP + (size_t)z * BB * 4 * HH;
    #pragma unroll
    for (int i = 0; i < 8; ++i) {
        int m = ty * 8 + i;
        *(float4*)&P[m * (4 * HH) + n0 + tx * 4] =
            make_float4(acc[i][0], acc[i][1], acc[i][2], acc[i][3]);
    }
#undef A_GT
#undef W_GT
}

// ---------------- LSTM: sum gate partials + biases, update h/c ----------------
__global__ void k_lstm(const float* __restrict__ bih, const float* __restrict__ bhh, int t) {
    int b = blockIdx.x, j = threadIdx.x;   // 512 threads
    if (g_dlen[b] <= t) return;
    float gs[4];
    #pragma unroll
    for (int gI = 0; gI < 4; ++gI) {
        int n = gI * HH + j;
        float s = bih[n] + bhh[n];
        #pragma unroll
        for (int z = 0; z < SP_GT; ++z)
            s += g_gatesP[((size_t)z * BB + b) * (4 * HH) + n];
        gs[gI] = s;
    }
    float ig = sigmf(gs[0]);
    float fg = sigmf(gs[1]);
    float gg = tanhf(gs[2]);
    float og = sigmf(gs[3]);
    float c = fg * g_c[b * HH + j] + ig * gg;
    g_c[b * HH + j] = c;
    g_h[b * HH + j] = og * tanhf(c);
}

// ---------------- logits GEMM + masked bounded write ----------------
__global__ __launch_bounds__(256) void k_logits(const float* __restrict__ fcW,
                                                const float* __restrict__ fcb,
                                                float* __restrict__ out, size_t cap, int t) {
#define A_LG(row, k) LD4(g_h[(row) * HH + (k)])
#define W_LG(row, k) LD4(fcW[(size_t)(n0 + (row)) * HH + (k)])
    GEMM2_BODY(A_LG, W_LG, 0, HH / TK, t);
    #pragma unroll
    for (int i = 0; i < 8; ++i) {
        int m = ty * 8 + i;
        bool act = g_dlen[m] > t;
        #pragma unroll
        for (int j = 0; j < 4; ++j) {
            int n = n0 + tx * 4 + j;
            float v = acc[i][j] + fcb[n];
            size_t idx = ((size_t)m * TT + t) * VV + n;
            if (idx < cap) out[idx] = act ? v : 0.f;
        }
    }
#undef A_LG
#undef W_LG
}

// ---------------- launch ----------------
extern "C" void kernel_launch(void* const* d_in, const int* in_sizes, int n_in,
                              void* d_out, int out_size) {
    if (n_in < 19) return;
    const float* enc  = (const float*)d_in[0];
    const int*   y32  = (const int*)d_in[1];
    const float* emb  = (const float*)d_in[2];
    const float* e2aW = (const float*)d_in[3];
    const float* h2aW = (const float*)d_in[4];
    const float* attW = (const float*)d_in[5];
    const float* attb = (const float*)d_in[6];
    const float* fbW  = (const float*)d_in[7];
    const float* fbb  = (const float*)d_in[8];
    const float* Wih  = (const float*)d_in[9];
    const float* bih  = (const float*)d_in[10];
    const float* Whh  = (const float*)d_in[11];
    const float* bhh  = (const float*)d_in[12];
    const float* fcW  = (const float*)d_in[13];
    const float* fcb  = (const float*)d_in[14];
    const float* ihW  = (const float*)d_in[15];
    const float* ihb  = (const float*)d_in[16];
    const float* icW  = (const float*)d_in[17];
    const float* icb  = (const float*)d_in[18];

    float* out = (float*)d_out;
    size_t cap = (size_t)out_size;

    k_sort<<<1, 64>>>(y32, out, cap);
    k_mean<<<dim3(BB, ENC / 256), 256>>>(enc);
    k_init_gemm<<<dim3(1024 / TN, 1, SP_INIT), 256>>>(ihW, icW);
    k_init_red<<<BB, 1024>>>(ihb, icb);
    k_att1<<<dim3(AA / TN, (BB * PP) / TM), 256>>>(enc, e2aW);

    for (int t = 0; t < TT; ++t) {
        k_att2<<<dim3(AA / TN, 1, SP_ATT2), 256>>>(h2aW, t);
        k_score<<<BB, 512>>>(attW, attb, out, cap, t);
        k_fgate<<<dim3(ENC / TN, 1, SP_FG), 256>>>(fbW, t);
        k_ctx<<<dim3(BB, ENC / 256), 256>>>(enc, fbb, t);
        k_gates<<<dim3((4 * HH) / TN, 1, SP_GT), 256>>>(y32, emb, Wih, Whh, t);
        k_lstm<<<BB, HH>>>(bih, bhh, t);
        k_logits<<<VV / TN, 256>>>(fcW, fcb, out, cap, t);
    }
}

// round 10
// speedup vs baseline: 4.8045x; 1.0520x over previous
#include <cuda_runtime.h>
#include <cuda_bf16.h>

// Problem dims (fixed)
#define BB 64
#define PP 196
#define ENC 2048
#define LL 20
#define TT 19
#define VV 32000
#define HH 512
#define EE 512
#define AA 512

#define PRED_SZ ((size_t)BB * TT * VV)
#define ALPHA_SZ ((size_t)BB * TT * PP)

// FFMA GEMM tile config (small kernels)
#define TM 64
#define TN 128
#define TK 16

// K-split factors
#define SP_INIT 8   // K=2048 -> chunks of 256
#define SP_ATT2 4   // K=512  -> chunks of 128
#define SP_FG   2   // K=512  -> chunks of 256
#define SP_GT   8   // K=3072 -> chunks of 384

// ---------------- scratch (device globals; no allocation) ----------------
__device__ int   g_sidx[BB];
__device__ int   g_dlen[BB];
__device__ int   g_ystride;
__device__ float g_mean[BB * ENC];
__device__ float g_h[BB * HH];
__device__ float g_c[BB * HH];
__device__ float g_att1[BB * PP * AA];            // 25.7 MB
__device__ float g_alpha[BB * PP];
__device__ float g_ctx[BB * ENC];
__device__ float g_initP[SP_INIT * BB * 1024];    // h|c partials
__device__ float g_att2P[SP_ATT2 * BB * AA];
__device__ float g_gateP[SP_FG * BB * ENC];
__device__ float g_gatesP[SP_GT * BB * 4 * HH];

__device__ __forceinline__ float sigmf(float x) { return 1.0f / (1.0f + expf(-x)); }

#define LD4(p) (*(const float4*)&(p))

// ---------------- bf16 split helpers ----------------
__device__ __forceinline__ void split2(float x0, float x1, unsigned& hi, unsigned& lo) {
    __nv_bfloat16 h0 = __float2bfloat16_rn(x0);
    __nv_bfloat16 h1 = __float2bfloat16_rn(x1);
    __nv_bfloat16 l0 = __float2bfloat16_rn(x0 - __bfloat162float(h0));
    __nv_bfloat16 l1 = __float2bfloat16_rn(x1 - __bfloat162float(h1));
    hi = ((unsigned)__bfloat16_as_ushort(h1) << 16) | __bfloat16_as_ushort(h0);
    lo = ((unsigned)__bfloat16_as_ushort(l1) << 16) | __bfloat16_as_ushort(l0);
}

__device__ __forceinline__ void mma_bf16(float c[4], unsigned a0, unsigned a1,
                                         unsigned a2, unsigned a3,
                                         unsigned b0, unsigned b1) {
    asm volatile(
        "mma.sync.aligned.m16n8k16.row.col.f32.bf16.bf16.f32 "
        "{%0,%1,%2,%3},{%4,%5,%6,%7},{%8,%9},{%0,%1,%2,%3};"
        : "+f"(c[0]), "+f"(c[1]), "+f"(c[2]), "+f"(c[3])
        : "r"(a0), "r"(a1), "r"(a2), "r"(a3), "r"(b0), "r"(b1));
}

// ---------------- MMA GEMM core: 64 x 128 tile, K in chunks of 32 ----------------
// AFETCH4(row,k): float4 of A[row][k..k+3], row 0..63 (k absolute)
// BFETCH4(row,k): float4 of W[n0+row][k..k+3], row 0..127
// Exposes: tid, n0, warp, lane, mw, nh, g, tig, acc c[8][4]
// Warp (mw,nh) owns rows mw*16..+16, cols nh*64..+64 (8 n-tiles of 8).
#define MMA_CORE(AFETCH4, BFETCH4, KSTART, KCHUNKS, TMASK)                      \
    __shared__ unsigned sAh[64][17], sAl[64][17];                               \
    __shared__ unsigned sBh[128][17], sBl[128][17];                             \
    int tid = threadIdx.x;                                                      \
    int n0 = blockIdx.x * 128;                                                  \
    int warp = tid >> 5, lane = tid & 31;                                       \
    int mw = warp >> 1, nh = warp & 1;                                          \
    int g = lane >> 2, tig = lane & 3;                                          \
    int ar = tid >> 2, aq = tid & 3;                                            \
    int br = tid >> 1, bq = tid & 1;                                            \
    int myact = (g_dlen[mw * 16] > (TMASK));                                    \
    float c[8][4];                                                              \
    _Pragma("unroll")                                                           \
    for (int i = 0; i < 8; ++i) c[i][0] = c[i][1] = c[i][2] = c[i][3] = 0.f;    \
    for (int kc = 0; kc < (KCHUNKS) * 32; kc += 32) {                           \
        {                                                                       \
            int ka = (KSTART) + kc + aq * 8;                                    \
            float4 f0 = AFETCH4(ar, ka);                                        \
            float4 f1 = AFETCH4(ar, (ka + 4));                                  \
            unsigned hi, lo;                                                    \
            split2(f0.x, f0.y, hi, lo); sAh[ar][aq*4+0]=hi; sAl[ar][aq*4+0]=lo; \
            split2(f0.z, f0.w, hi, lo); sAh[ar][aq*4+1]=hi; sAl[ar][aq*4+1]=lo; \
            split2(f1.x, f1.y, hi, lo); sAh[ar][aq*4+2]=hi; sAl[ar][aq*4+2]=lo; \
            split2(f1.z, f1.w, hi, lo); sAh[ar][aq*4+3]=hi; sAl[ar][aq*4+3]=lo; \
            int kb = (KSTART) + kc + bq * 16;                                   \
            float4 g0 = BFETCH4(br, kb);                                        \
            float4 g1 = BFETCH4(br, (kb + 4));                                  \
            float4 g2 = BFETCH4(br, (kb + 8));                                  \
            float4 g3 = BFETCH4(br, (kb + 12));                                 \
            split2(g0.x,g0.y,hi,lo); sBh[br][bq*8+0]=hi; sBl[br][bq*8+0]=lo;    \
            split2(g0.z,g0.w,hi,lo); sBh[br][bq*8+1]=hi; sBl[br][bq*8+1]=lo;    \
            split2(g1.x,g1.y,hi,lo); sBh[br][bq*8+2]=hi; sBl[br][bq*8+2]=lo;    \
            split2(g1.z,g1.w,hi,lo); sBh[br][bq*8+3]=hi; sBl[br][bq*8+3]=lo;    \
            split2(g2.x,g2.y,hi,lo); sBh[br][bq*8+4]=hi; sBl[br][bq*8+4]=lo;    \
            split2(g2.z,g2.w,hi,lo); sBh[br][bq*8+5]=hi; sBl[br][bq*8+5]=lo;    \
            split2(g3.x,g3.y,hi,lo); sBh[br][bq*8+6]=hi; sBl[br][bq*8+6]=lo;    \
            split2(g3.z,g3.w,hi,lo); sBh[br][bq*8+7]=hi; sBl[br][bq*8+7]=lo;    \
        }                                                                       \
        __syncthreads();                                                        \
        if (myact) {                                                            \
            _Pragma("unroll")                                                   \
            for (int ks = 0; ks < 2; ++ks) {                                    \
                int kb = ks * 8;                                                \
                int r0 = mw * 16 + g, r1 = r0 + 8;                              \
                unsigned a0 = sAh[r0][kb+tig],   a1 = sAh[r1][kb+tig];          \
                unsigned a2 = sAh[r0][kb+4+tig], a3 = sAh[r1][kb+4+tig];        \
                unsigned l0 = sAl[r0][kb+tig],   l1 = sAl[r1][kb+tig];          \
                unsigned l2 = sAl[r0][kb+4+tig], l3 = sAl[r1][kb+4+tig];        \
                _Pragma("unroll")                                               \
                for (int nt = 0; nt < 8; ++nt) {                                \
                    int colr = nh * 64 + nt * 8 + g;                            \
                    unsigned b0 = sBh[colr][kb+tig], b1 = sBh[colr][kb+4+tig];  \
                    unsigned lb0 = sBl[colr][kb+tig], lb1 = sBl[colr][kb+4+tig];\
                    mma_bf16(c[nt], a0, a1, a2, a3, b0, b1);                    \
                    mma_bf16(c[nt], l0, l1, l2, l3, b0, b1);                    \
                    mma_bf16(c[nt], a0, a1, a2, a3, lb0, lb1);                  \
                }                                                               \
            }                                                                   \
        }                                                                       \
        __syncthreads();                                                        \
    }

// ---------------- FFMA GEMM body (kept for small kernels) ----------------
#define GEMM2_BODY(AFETCH4, WFETCH4, KSTART, KTILES, TMASK)                     \
    __shared__ float As[2][TK][TM + 4];                                         \
    __shared__ float Ws[2][TK][TN + 4];                                         \
    int tid = threadIdx.x;                                                      \
    int tx = tid & 31, ty = tid >> 5;                                           \
    int n0 = blockIdx.x * TN;                                                   \
    int arow = tid >> 2, kq = tid & 3;                                          \
    int brow0 = tid >> 2, brow1 = (tid >> 2) + 64;                              \
    int myact = (g_dlen[ty * 8] > (TMASK));                                     \
    float acc[8][4] = {};                                                       \
    float4 rA, rB0, rB1;                                                        \
    {                                                                           \
        int k = (KSTART) + kq * 4;                                              \
        rA = AFETCH4(arow, k);                                                  \
        rB0 = WFETCH4(brow0, k);                                                \
        rB1 = WFETCH4(brow1, k);                                                \
    }                                                                           \
    As[0][kq * 4 + 0][arow] = rA.x;  As[0][kq * 4 + 1][arow] = rA.y;            \
    As[0][kq * 4 + 2][arow] = rA.z;  As[0][kq * 4 + 3][arow] = rA.w;            \
    Ws[0][kq * 4 + 0][brow0] = rB0.x; Ws[0][kq * 4 + 1][brow0] = rB0.y;         \
    Ws[0][kq * 4 + 2][brow0] = rB0.z; Ws[0][kq * 4 + 3][brow0] = rB0.w;         \
    Ws[0][kq * 4 + 0][brow1] = rB1.x; Ws[0][kq * 4 + 1][brow1] = rB1.y;         \
    Ws[0][kq * 4 + 2][brow1] = rB1.z; Ws[0][kq * 4 + 3][brow1] = rB1.w;         \
    __syncthreads();                                                            \
    for (int tile = 0; tile < (KTILES); ++tile) {                               \
        int buf = tile & 1;                                                     \
        bool more = (tile + 1) < (KTILES);                                      \
        if (more) {                                                             \
            int k = (KSTART) + (tile + 1) * TK + kq * 4;                        \
            rA = AFETCH4(arow, k);                                              \
            rB0 = WFETCH4(brow0, k);                                            \
            rB1 = WFETCH4(brow1, k);                                            \
        }                                                                       \
        if (myact) {                                                            \
            _Pragma("unroll")                                                   \
            for (int kk = 0; kk < TK; ++kk) {                                   \
                float4 a0 = *(const float4*)&As[buf][kk][ty * 8];               \
                float4 a1 = *(const float4*)&As[buf][kk][ty * 8 + 4];           \
                float4 wv = *(const float4*)&Ws[buf][kk][tx * 4];               \
                float av[8] = {a0.x, a0.y, a0.z, a0.w, a1.x, a1.y, a1.z, a1.w}; \
                float wr[4] = {wv.x, wv.y, wv.z, wv.w};                         \
                _Pragma("unroll")                                               \
                for (int i = 0; i < 8; ++i)                                     \
                    _Pragma("unroll")                                           \
                    for (int j = 0; j < 4; ++j) acc[i][j] += av[i] * wr[j];     \
            }                                                                   \
        }                                                                       \
        __syncthreads();                                                        \
        if (more) {                                                             \
            int nb = buf ^ 1;                                                   \
            As[nb][kq * 4 + 0][arow] = rA.x;  As[nb][kq * 4 + 1][arow] = rA.y;  \
            As[nb][kq * 4 + 2][arow] = rA.z;  As[nb][kq * 4 + 3][arow] = rA.w;  \
            Ws[nb][kq * 4 + 0][brow0] = rB0.x; Ws[nb][kq * 4 + 1][brow0] = rB0.y;\
            Ws[nb][kq * 4 + 2][brow0] = rB0.z; Ws[nb][kq * 4 + 3][brow0] = rB0.w;\
            Ws[nb][kq * 4 + 0][brow1] = rB1.x; Ws[nb][kq * 4 + 1][brow1] = rB1.y;\
            Ws[nb][kq * 4 + 2][brow1] = rB1.z; Ws[nb][kq * 4 + 3][brow1] = rB1.w;\
            __syncthreads();                                                    \
        }                                                                       \
    }

// ---------------- sort / layout detect ----------------
__global__ void k_sort(const int* __restrict__ y32, float* __restrict__ out, size_t cap) {
    __shared__ int len[BB];
    __shared__ int stride_s;
    int i = threadIdx.x;
    if (i == 0) {
        int odd = 0;
        for (int l = 0; l < LL; ++l) odd |= (y32[2 * l + 1] != 0);
        stride_s = odd ? 1 : 2;
        g_ystride = stride_s;
    }
    __syncthreads();
    int stride = stride_s;
    if (i < BB) {
        int c = 0;
        for (int l = 0; l < LL; ++l) c += (y32[(i * LL + l) * stride] != 0);
        len[i] = c;
    }
    __syncthreads();
    if (i < BB) {
        int r = 0;
        for (int j = 0; j < BB; ++j)
            r += (len[j] > len[i]) || (len[j] == len[i] && j < i);
        g_sidx[r] = i;
        g_dlen[r] = len[i] - 1;
        size_t base = PRED_SZ + ALPHA_SZ;
        if (base + r < cap)      out[base + r]      = (float)(len[i] - 1);
        if (base + BB + r < cap) out[base + BB + r] = (float)i;
    }
}

// ---------------- mean over P ----------------
__global__ void k_mean(const float* __restrict__ enc) {
    int b = blockIdx.x;
    int e = blockIdx.y * 256 + threadIdx.x;
    const float* base = enc + (size_t)g_sidx[b] * PP * ENC + e;
    float s = 0.f;
    #pragma unroll 8
    for (int p = 0; p < PP; ++p) s += base[p * ENC];
    g_mean[b * ENC + e] = s * (1.0f / PP);
}

// ---------------- init h0/c0 fused GEMM (N=1024), K-split x8 ----------------
__global__ __launch_bounds__(256) void k_init_gemm(const float* __restrict__ ihW,
                                                   const float* __restrict__ icW) {
    int z = blockIdx.z;
#define A_INIT(row, k) LD4(g_mean[(row) * ENC + (k)])
#define W_INIT(row, k) ((n0 + (row)) < HH ? LD4(ihW[(n0 + (row)) * ENC + (k)]) \
                                          : LD4(icW[(n0 + (row) - HH) * ENC + (k)]))
    GEMM2_BODY(A_INIT, W_INIT, z * (ENC / SP_INIT), (ENC / SP_INIT) / TK, -1);
    float* P = g_initP + (size_t)z * BB * 1024;
    #pragma unroll
    for (int i = 0; i < 8; ++i) {
        int m = ty * 8 + i;
        *(float4*)&P[m * 1024 + n0 + tx * 4] =
            make_float4(acc[i][0], acc[i][1], acc[i][2], acc[i][3]);
    }
#undef A_INIT
#undef W_INIT
}

__global__ void k_init_red(const float* __restrict__ ihb, const float* __restrict__ icb) {
    int b = blockIdx.x, n = threadIdx.x;    // 1024 threads
    float s = 0.f;
    #pragma unroll
    for (int z = 0; z < SP_INIT; ++z) s += g_initP[((size_t)z * BB + b) * 1024 + n];
    if (n < HH) g_h[b * HH + n] = s + ihb[n];
    else        g_c[b * HH + (n - HH)] = s + icb[n - HH];
}

// ---------------- att1 (MMA): enc_sorted @ enc2att_W^T ----------------
__global__ __launch_bounds__(256) void k_att1_mma(const float* __restrict__ enc,
                                                  const float* __restrict__ Wq) {
    __shared__ int rowOff[64];
    int m0 = blockIdx.y * 64;
    if (threadIdx.x < 64) {
        int m = m0 + threadIdx.x;
        int b = m / PP, p = m % PP;
        rowOff[threadIdx.x] = (g_sidx[b] * PP + p) * ENC;
    }
    __syncthreads();
#define A_A1(row, k) LD4(enc[rowOff[(row)] + (k)])
#define W_A1(row, k) LD4(Wq[(n0 + (row)) * ENC + (k)])
    MMA_CORE(A_A1, W_A1, 0, ENC / 32, -1);
    #pragma unroll
    for (int nt = 0; nt < 8; ++nt) {
        int col = n0 + nh * 64 + nt * 8 + 2 * tig;
        int r0 = mw * 16 + g, r1 = r0 + 8;
        g_att1[(size_t)(m0 + r0) * AA + col]     = c[nt][0];
        g_att1[(size_t)(m0 + r0) * AA + col + 1] = c[nt][1];
        g_att1[(size_t)(m0 + r1) * AA + col]     = c[nt][2];
        g_att1[(size_t)(m0 + r1) * AA + col + 1] = c[nt][3];
    }
#undef A_A1
#undef W_A1
}

// ---------------- att2 partials: h @ h2aW^T, K-split x4, masked by t ----------------
__global__ __launch_bounds__(256) void k_att2(const float* __restrict__ W, int t) {
    int z = blockIdx.z;
#define A_A2(row, k) LD4(g_h[(row) * HH + (k)])
#define W_A2(row, k) LD4(W[(n0 + (row)) * HH + (k)])
    GEMM2_BODY(A_A2, W_A2, z * (HH / SP_ATT2), (HH / SP_ATT2) / TK, t);
    float* P = g_att2P + (size_t)z * BB * AA;
    #pragma unroll
    for (int i = 0; i < 8; ++i) {
        int m = ty * 8 + i;
        *(float4*)&P[m * AA + n0 + tx * 4] =
            make_float4(acc[i][0], acc[i][1], acc[i][2], acc[i][3]);
    }
#undef A_A2
#undef W_A2
}

// ---------------- score + softmax + alpha (skips inactive rows) ----------------
__global__ __launch_bounds__(512) void k_score(const float* __restrict__ attW,
                                               const float* __restrict__ attb,
                                               float* __restrict__ out, size_t cap, int t) {
    __shared__ float a2[AA];
    __shared__ float aw[AA];
    __shared__ float sc[PP];
    __shared__ float red[2];
    int b = blockIdx.x, tid = threadIdx.x;
    if (g_dlen[b] <= t) {
        for (int p = tid; p < PP; p += 512) {
            size_t idx = PRED_SZ + (size_t)(b * TT + t) * PP + p;
            if (idx < cap) out[idx] = 0.f;
        }
        return;
    }
    for (int i = tid; i < AA; i += 512) {
        float s = 0.f;
        #pragma unroll
        for (int z = 0; z < SP_ATT2; ++z) s += g_att2P[((size_t)z * BB + b) * AA + i];
        a2[i] = s;
        aw[i] = attW[i];
    }
    __syncthreads();
    int w = tid >> 5, lane = tid & 31;
    for (int p = w; p < PP; p += 16) {
        const float* base = g_att1 + (size_t)(b * PP + p) * AA;
        float s = 0.f;
        #pragma unroll 4
        for (int a0 = lane; a0 < AA; a0 += 32) {
            float v = base[a0] + a2[a0];
            s += fmaxf(v, 0.f) * aw[a0];
        }
        #pragma unroll
        for (int o = 16; o; o >>= 1) s += __shfl_down_sync(0xFFFFFFFFu, s, o);
        if (lane == 0) sc[p] = s + attb[0];
    }
    __syncthreads();
    if (w == 0) {
        float mx = -1e30f;
        for (int p = lane; p < PP; p += 32) mx = fmaxf(mx, sc[p]);
        #pragma unroll
        for (int o = 16; o; o >>= 1) mx = fmaxf(mx, __shfl_xor_sync(0xFFFFFFFFu, mx, o));
        float sm = 0.f;
        for (int p = lane; p < PP; p += 32) sm += expf(sc[p] - mx);
        #pragma unroll
        for (int o = 16; o; o >>= 1) sm += __shfl_xor_sync(0xFFFFFFFFu, sm, o);
        if (lane == 0) { red[0] = mx; red[1] = 1.0f / sm; }
    }
    __syncthreads();
    float mx = red[0], inv = red[1];
    for (int p = tid; p < PP; p += 512) {
        float al = expf(sc[p] - mx) * inv;
        g_alpha[b * PP + p] = al;
        size_t idx = PRED_SZ + (size_t)(b * TT + t) * PP + p;
        if (idx < cap) out[idx] = al;
    }
}

// ---------------- fgate partials: h @ fbW^T, K-split x2, masked by t ----------------
__global__ __launch_bounds__(256) void k_fgate(const float* __restrict__ W, int t) {
    int z = blockIdx.z;
#define A_FG(row, k) LD4(g_h[(row) * HH + (k)])
#define W_FG(row, k) LD4(W[(n0 + (row)) * HH + (k)])
    GEMM2_BODY(A_FG, W_FG, z * (HH / SP_FG), (HH / SP_FG) / TK, t);
    float* P = g_gateP + (size_t)z * BB * ENC;
    #pragma unroll
    for (int i = 0; i < 8; ++i) {
        int m = ty * 8 + i;
        *(float4*)&P[m * ENC + n0 + tx * 4] =
            make_float4(acc[i][0], acc[i][1], acc[i][2], acc[i][3]);
    }
#undef A_FG
#undef W_FG
}

// ---------------- context: ctx = sigmoid(gateSum+b) * (alpha @ enc) ----------------
__global__ void k_ctx(const float* __restrict__ enc, const float* __restrict__ fbb, int t) {
    __shared__ float al[PP];
    int b = blockIdx.x;
    if (g_dlen[b] <= t) return;
    int e = blockIdx.y * 256 + threadIdx.x;
    if (threadIdx.x < PP) al[threadIdx.x] = g_alpha[b * PP + threadIdx.x];
    __syncthreads();
    const float* base = enc + (size_t)g_sidx[b] * PP * ENC + e;
    float s = 0.f;
    #pragma unroll 8
    for (int p = 0; p < PP; ++p) s += al[p] * base[p * ENC];
    float gr = g_gateP[b * ENC + e] + g_gateP[(size_t)BB * ENC + b * ENC + e] + fbb[e];
    g_ctx[b * ENC + e] = sigmf(gr) * s;
}

// ---------------- LSTM gates (MMA): [emb|ctx|h] @ [W_ih;W_hh]^T, K-split x8 ----------------
__global__ __launch_bounds__(256) void k_gates_mma(const int* __restrict__ y32,
                                                   const float* __restrict__ emb,
                                                   const float* __restrict__ Wih,
                                                   const float* __restrict__ Whh,
                                                   int t) {
    __shared__ int tokOff[64];
    if (threadIdx.x < 64) {
        int tok = y32[(g_sidx[threadIdx.x] * LL + t) * g_ystride];
        tok = max(0, min(tok, VV - 1));
        tokOff[threadIdx.x] = tok * EE;
    }
    __syncthreads();
    int z = blockIdx.z;
#define A_GT(row, k) ((k) < EE ? LD4(emb[tokOff[(row)] + (k)])                       \
                     : (k) < EE + ENC ? LD4(g_ctx[(row) * ENC + ((k) - EE)])         \
                                      : LD4(g_h[(row) * HH + ((k) - EE - ENC)]))
#define W_GT(row, k) ((k) < EE + ENC ? LD4(Wih[(size_t)(n0 + (row)) * (EE + ENC) + (k)]) \
                                     : LD4(Whh[(n0 + (row)) * HH + ((k) - EE - ENC)]))
    MMA_CORE(A_GT, W_GT, z * ((EE + ENC + HH) / SP_GT), ((EE + ENC + HH) / SP_GT) / 32, t);
    float* P = g_gatesP + (size_t)z * BB * 4 * HH;
    #pragma unroll
    for (int nt = 0; nt < 8; ++nt) {
        int col = n0 + nh * 64 + nt * 8 + 2 * tig;
        int r0 = mw * 16 + g, r1 = r0 + 8;
        P[r0 * (4 * HH) + col]     = c[nt][0];
        P[r0 * (4 * HH) + col + 1] = c[nt][1];
        P[r1 * (4 * HH) + col]     = c[nt][2];
        P[r1 * (4 * HH) + col + 1] = c[nt][3];
    }
#undef A_GT
#undef W_GT
}

// ---------------- LSTM: sum gate partials + biases, update h/c ----------------
__global__ void k_lstm(const float* __restrict__ bih, const float* __restrict__ bhh, int t) {
    int b = blockIdx.x, j = threadIdx.x;   // 512 threads
    if (g_dlen[b] <= t) return;
    float gs[4];
    #pragma unroll
    for (int gI = 0; gI < 4; ++gI) {
        int n = gI * HH + j;
        float s = bih[n] + bhh[n];
        #pragma unroll
        for (int z = 0; z < SP_GT; ++z)
            s += g_gatesP[((size_t)z * BB + b) * (4 * HH) + n];
        gs[gI] = s;
    }
    float ig = sigmf(gs[0]);
    float fg = sigmf(gs[1]);
    float gg = tanhf(gs[2]);
    float og = sigmf(gs[3]);
    float c = fg * g_c[b * HH + j] + ig * gg;
    g_c[b * HH + j] = c;
    g_h[b * HH + j] = og * tanhf(c);
}

// ---------------- logits (MMA) + masked bounded write ----------------
__global__ __launch_bounds__(256) void k_logits_mma(const float* __restrict__ fcW,
                                                    const float* __restrict__ fcb,
                                                    float* __restrict__ out, size_t cap, int t) {
#define A_LG(row, k) LD4(g_h[(row) * HH + (k)])
#define W_LG(row, k) LD4(fcW[(size_t)(n0 + (row)) * HH + (k)])
    MMA_CORE(A_LG, W_LG, 0, HH / 32, t);
    #pragma unroll
    for (int nt = 0; nt < 8; ++nt) {
        int col = n0 + nh * 64 + nt * 8 + 2 * tig;
        int r0 = mw * 16 + g, r1 = r0 + 8;
        bool act0 = g_dlen[r0] > t, act1 = g_dlen[r1] > t;
        size_t i00 = ((size_t)r0 * TT + t) * VV + col;
        size_t i10 = ((size_t)r1 * TT + t) * VV + col;
        if (i00 + 1 < cap) {
            out[i00]     = act0 ? c[nt][0] + fcb[col]     : 0.f;
            out[i00 + 1] = act0 ? c[nt][1] + fcb[col + 1] : 0.f;
        }
        if (i10 + 1 < cap) {
            out[i10]     = act1 ? c[nt][2] + fcb[col]     : 0.f;
            out[i10 + 1] = act1 ? c[nt][3] + fcb[col + 1] : 0.f;
        }
    }
#undef A_LG
#undef W_LG
}

// ---------------- launch ----------------
extern "C" void kernel_launch(void* const* d_in, const int* in_sizes, int n_in,
                              void* d_out, int out_size) {
    if (n_in < 19) return;
    const float* enc  = (const float*)d_in[0];
    const int*   y32  = (const int*)d_in[1];
    const float* emb  = (const float*)d_in[2];
    const float* e2aW = (const float*)d_in[3];
    const float* h2aW = (const float*)d_in[4];
    const float* attW = (const float*)d_in[5];
    const float* attb = (const float*)d_in[6];
    const float* fbW  = (const float*)d_in[7];
    const float* fbb  = (const float*)d_in[8];
    const float* Wih  = (const float*)d_in[9];
    const float* bih  = (const float*)d_in[10];
    const float* Whh  = (const float*)d_in[11];
    const float* bhh  = (const float*)d_in[12];
    const float* fcW  = (const float*)d_in[13];
    const float* fcb  = (const float*)d_in[14];
    const float* ihW  = (const float*)d_in[15];
    const float* ihb  = (const float*)d_in[16];
    const float* icW  = (const float*)d_in[17];
    const float* icb  = (const float*)d_in[18];

    float* out = (float*)d_out;
    size_t cap = (size_t)out_size;

    k_sort<<<1, 64>>>(y32, out, cap);
    k_mean<<<dim3(BB, ENC / 256), 256>>>(enc);
    k_init_gemm<<<dim3(1024 / TN, 1, SP_INIT), 256>>>(ihW, icW);
    k_init_red<<<BB, 1024>>>(ihb, icb);
    k_att1_mma<<<dim3(AA / 128, (BB * PP) / 64), 256>>>(enc, e2aW);

    for (int t = 0; t < TT; ++t) {
        k_att2<<<dim3(AA / TN, 1, SP_ATT2), 256>>>(h2aW, t);
        k_score<<<BB, 512>>>(attW, attb, out, cap, t);
        k_fgate<<<dim3(ENC / TN, 1, SP_FG), 256>>>(fbW, t);
        k_ctx<<<dim3(BB, ENC / 256), 256>>>(enc, fbb, t);
        k_gates_mma<<<dim3((4 * HH) / 128, 1, SP_GT), 256>>>(y32, emb, Wih, Whh, t);
        k_lstm<<<BB, HH>>>(bih, bhh, t);
        k_logits_mma<<<VV / 128, 256>>>(fcW, fcb, out, cap, t);
    }
}